// round 15
// baseline (speedup 1.0000x reference)
#include <cuda_runtime.h>
#include <cuda_fp16.h>
#include <cuda_bf16.h>
#include <cstdint>

// ---------------------------------------------------------------------------
// TriplaneEncoder: out[n][c] = sum_{p=0..2} bilinear(C_mat[p], coords_p(n))[c]
// Planes: p0:(x0,x1), p1:(x0,x2), p2:(x1,x2); gx = first (W axis), gy = second (H).
// align_corners=False, zero padding. RES=512, C=32, N=2097152.
//
// R14: R13 structure (8-lane 128B span gather, 2 pts/thread, MLP=12) with the
//      instruction-bound fat trimmed:
//   - packed fma.rn.f32x2 (FFMA2) accumulation: halves hot-path FFMA count
//   - 32-bit shift-form table offsets (plane stride = 1<<23 elements)
//   - 1-FMA coordinate transform
// ---------------------------------------------------------------------------

#define RES   512
#define CFEAT 32

// 48 MB pixel-major fp16 table, +64 halves pad for the dead (weight-0) overread
// at bx=511 hiX span loads.
__device__ __half g_Th[3 * RES * RES * CFEAT + 64];

// ---------------------------------------------------------------------------
// Transpose+convert: src [p][c][y][x] f32 -> dst [p][y][x][c] f16.
// Block 256. grid = (16, 512, 3).
// ---------------------------------------------------------------------------
__global__ __launch_bounds__(256)
void transpose_kernel(const float* __restrict__ src)
{
    __shared__ float tile[32][33];   // [c][x], padded

    const int p  = blockIdx.z;
    const int y  = blockIdx.y;
    const int x0 = blockIdx.x * 32;
    const int t  = threadIdx.x;
    const int tx = t & 31;
    const int ty = t >> 5;

    const float* sp = src + ((size_t)p * CFEAT) * (RES * RES) + (size_t)y * RES + x0;
    #pragma unroll
    for (int c = ty; c < 32; c += 8) {
        tile[c][tx] = sp[(size_t)c * (RES * RES) + tx];
    }
    __syncthreads();

    const int xi  = t >> 3;              // 0..31 pixel within tile
    const int seg = t & 7;               // 0..7 channel quad

    struct __align__(8) H4 { __half2 a, b; };
    H4 packed;
    packed.a = __floats2half2_rn(tile[4 * seg + 0][xi], tile[4 * seg + 1][xi]);
    packed.b = __floats2half2_rn(tile[4 * seg + 2][xi], tile[4 * seg + 3][xi]);

    __half* dp = g_Th + (((size_t)p * RES + y) * RES + x0) * CFEAT;
    *reinterpret_cast<H4*>(dp + (size_t)xi * CFEAT + seg * 4) = packed;
}

// ---------------------------------------------------------------------------
// Packed f32x2 helpers (Blackwell FFMA2 is PTX-only)
// ---------------------------------------------------------------------------
__device__ __forceinline__ uint64_t pack_f32x2(float lo, float hi)
{
    uint64_t r;
    asm("mov.b64 %0, {%1, %2};" : "=l"(r) : "r"(__float_as_uint(lo)), "r"(__float_as_uint(hi)));
    return r;
}
__device__ __forceinline__ void unpack_f32x2(uint64_t v, float& lo, float& hi)
{
    uint32_t a, b;
    asm("mov.b64 {%0, %1}, %2;" : "=r"(a), "=r"(b) : "l"(v));
    lo = __uint_as_float(a);
    hi = __uint_as_float(b);
}
__device__ __forceinline__ void fma_f32x2(uint64_t& acc, uint64_t a, uint64_t b)
{
    asm("fma.rn.f32x2 %0, %1, %2, %0;" : "+l"(acc) : "l"(a), "l"(b));
}

// acc: 4 packed f32x2 (8 channels). One 16B span-piece, weight w.
__device__ __forceinline__ void accum_span(uint64_t acc[4], const __half* __restrict__ ptr, float w)
{
    const uint4 raw = __ldg(reinterpret_cast<const uint4*>(ptr));
    const __half2* h2 = reinterpret_cast<const __half2*>(&raw);
    const uint64_t w2 = pack_f32x2(w, w);
    #pragma unroll
    for (int i = 0; i < 4; ++i) {
        float2 f = __half22float2(h2[i]);
        fma_f32x2(acc[i], pack_f32x2(f.x, f.y), w2);
    }
}

// One plane's two row-span loads for one point. Tp pre-offset by lane*8.
__device__ __forceinline__ void plane_sample(uint64_t acc[4], const __half* __restrict__ Tp,
                                             float gx, float gy, bool hiX)
{
    // ((g+1)*512 - 1) * 0.5 == g*256 + 255.5
    const float ix = fmaf(gx, 256.0f, 255.5f);
    const float iy = fmaf(gy, 256.0f, 255.5f);

    const float x0f = floorf(ix);
    const float y0f = floorf(iy);
    const float wx1 = ix - x0f, wx0 = 1.0f - wx1;
    const float wy1 = iy - y0f, wy0 = 1.0f - wy1;

    const int xi0 = (int)x0f;            // in [-1, 511]
    const int yi0 = (int)y0f;            // in [-1, 511]

    const unsigned bx = (unsigned)max(xi0, 0);
    const float wA = (xi0 >= 0) ? wx0 : wx1;                  // xi0==-1: base IS the x1 pixel
    const float wB = (xi0 >= 0 && xi0 < RES - 1) ? wx1 : 0.f;
    const float wlx = hiX ? wB : wA;

    const unsigned rA = (unsigned)max(yi0, 0);
    const float    vA = (yi0 >= 0) ? wy0 : 0.f;
    const unsigned rB = (unsigned)min(yi0 + 1, RES - 1);
    const float    vB = (yi0 + 1 <= RES - 1) ? wy1 : 0.f;

    // element offsets: (r*512 + bx)*32 = (r<<14) + (bx<<5)
    const unsigned offA = (rA << 14) + (bx << 5);
    const unsigned offB = (rB << 14) + (bx << 5);
    accum_span(acc, Tp + offA, wlx * vA);
    accum_span(acc, Tp + offB, wlx * vB);
}

__global__ __launch_bounds__(256)
void sample_kernel(const float* __restrict__ x, float* __restrict__ out, int half)
{
    const int gid  = blockIdx.x * blockDim.x + threadIdx.x;
    const int grp  = gid >> 3;           // 8-lane group
    const int lane = gid & 7;
    if (grp >= half) return;

    const int  pt0 = grp;
    const int  pt1 = grp + half;
    const bool hiX = (lane >= 4);

    // coords (broadcast across the 8 lanes of each group)
    const float a0 = __ldg(x + (size_t)pt0 * 3 + 0);
    const float a1 = __ldg(x + (size_t)pt0 * 3 + 1);
    const float a2 = __ldg(x + (size_t)pt0 * 3 + 2);
    const float b0 = __ldg(x + (size_t)pt1 * 3 + 0);
    const float b1 = __ldg(x + (size_t)pt1 * 3 + 1);
    const float b2 = __ldg(x + (size_t)pt1 * 3 + 2);

    const float gxsA[3] = { a0, a0, a1 };
    const float gysA[3] = { a1, a2, a2 };
    const float gxsB[3] = { b0, b0, b1 };
    const float gysB[3] = { b1, b2, b2 };

    uint64_t acc0[4], acc1[4];
    const uint64_t z = pack_f32x2(0.f, 0.f);
    #pragma unroll
    for (int i = 0; i < 4; ++i) { acc0[i] = z; acc1[i] = z; }

    const __half* Tl = g_Th + lane * 8;
    #pragma unroll
    for (int p = 0; p < 3; ++p) {
        const __half* Tp = Tl + ((unsigned)p << 23);   // p * 512*512*32
        plane_sample(acc0, Tp, gxsA[p], gysA[p], hiX);
        plane_sample(acc1, Tp, gxsB[p], gysB[p], hiX);
    }

    // Unpack and combine x0/x1 halves (lanes l and l^4 hold partials for group l&3)
    float f0[8], f1[8];
    #pragma unroll
    for (int i = 0; i < 4; ++i) {
        unpack_f32x2(acc0[i], f0[2 * i], f0[2 * i + 1]);
        unpack_f32x2(acc1[i], f1[2 * i], f1[2 * i + 1]);
    }
    #pragma unroll
    for (int i = 0; i < 8; ++i) {
        f0[i] += __shfl_xor_sync(0xffffffff, f0[i], 4);
        f1[i] += __shfl_xor_sync(0xffffffff, f1[i], 4);
    }

    const int g = lane & 3;
    const int off = g * 8 + (hiX ? 4 : 0);
    float4 v0 = hiX ? make_float4(f0[4], f0[5], f0[6], f0[7])
                    : make_float4(f0[0], f0[1], f0[2], f0[3]);
    float4 v1 = hiX ? make_float4(f1[4], f1[5], f1[6], f1[7])
                    : make_float4(f1[0], f1[1], f1[2], f1[3]);
    __stwt(reinterpret_cast<float4*>(out + (size_t)pt0 * CFEAT + off), v0);
    __stwt(reinterpret_cast<float4*>(out + (size_t)pt1 * CFEAT + off), v1);
}

// ---------------------------------------------------------------------------
extern "C" void kernel_launch(void* const* d_in, const int* in_sizes, int n_in,
                              void* d_out, int out_size)
{
    const float* x_in  = (const float*)d_in[0];   // [N, 3]
    const float* c_mat = (const float*)d_in[1];   // [3, 32, 512, 512]
    float* out = (float*)d_out;                   // [N, 32]

    const int npts = in_sizes[0] / 3;
    const int half = npts / 2;

    dim3 tg(RES / 32, RES, 3);
    transpose_kernel<<<tg, 256>>>(c_mat);

    const int threads = 256;
    const long long total = (long long)half * 8;
    const int blocks = (int)((total + threads - 1) / threads);
    sample_kernel<<<blocks, threads>>>(x_in, out, half);
}

// round 16
// speedup vs baseline: 1.4052x; 1.4052x over previous
#include <cuda_runtime.h>
#include <cuda_fp16.h>
#include <cuda_bf16.h>
#include <cstdint>

// ---------------------------------------------------------------------------
// TriplaneEncoder: out[n][c] = sum_{p=0..2} bilinear(C_mat[p], coords_p(n))[c]
// Planes: p0:(x0,x1), p1:(x0,x2), p2:(x1,x2); gx = first (W axis), gy = second (H).
// align_corners=False, zero padding. RES=512, C=32, N=2097152.
//
// R15: R13 structure (8-lane 128B span gather, 2 pts/thread, MLP=12) with:
//   - fp16 y-blend: rowA*vA + rowB*vB in half2 (HMUL2+HFMA2), ONE convert,
//     one fp32 FMA with x-weight -> ~25% fewer hot-path instructions
//   - 1-FMA coord transform, 32-bit shift-form offsets
//   - __launch_bounds__(256,6): regs<=40, occ 52% -> 75% to hide gather latency
//   (R14's f32x2 experiment reverted: mov.b64 pair-marshalling cost > FFMA2 win)
// ---------------------------------------------------------------------------

#define RES   512
#define CFEAT 32

// 48 MB pixel-major fp16 table, +64 halves pad for the dead (weight-0) overread
// at bx=511 hiX span loads.
__device__ __half g_Th[3 * RES * RES * CFEAT + 64];

// ---------------------------------------------------------------------------
// Transpose+convert: src [p][c][y][x] f32 -> dst [p][y][x][c] f16.
// Block 256. grid = (16, 512, 3).
// ---------------------------------------------------------------------------
__global__ __launch_bounds__(256)
void transpose_kernel(const float* __restrict__ src)
{
    __shared__ float tile[32][33];   // [c][x], padded

    const int p  = blockIdx.z;
    const int y  = blockIdx.y;
    const int x0 = blockIdx.x * 32;
    const int t  = threadIdx.x;
    const int tx = t & 31;
    const int ty = t >> 5;

    const float* sp = src + ((size_t)p * CFEAT) * (RES * RES) + (size_t)y * RES + x0;
    #pragma unroll
    for (int c = ty; c < 32; c += 8) {
        tile[c][tx] = sp[(size_t)c * (RES * RES) + tx];
    }
    __syncthreads();

    const int xi  = t >> 3;              // 0..31 pixel within tile
    const int seg = t & 7;               // 0..7 channel quad

    struct __align__(8) H4 { __half2 a, b; };
    H4 packed;
    packed.a = __floats2half2_rn(tile[4 * seg + 0][xi], tile[4 * seg + 1][xi]);
    packed.b = __floats2half2_rn(tile[4 * seg + 2][xi], tile[4 * seg + 3][xi]);

    __half* dp = g_Th + (((size_t)p * RES + y) * RES + x0) * CFEAT;
    *reinterpret_cast<H4*>(dp + (size_t)xi * CFEAT + seg * 4) = packed;
}

// ---------------------------------------------------------------------------
// Sample kernel
// ---------------------------------------------------------------------------

// One plane for one point: two row-span loads, fp16 y-blend, fp32 x-weight FMA.
// Tp pre-offset by lane*8 halves.
__device__ __forceinline__ void plane_sample(float acc[8], const __half* __restrict__ Tp,
                                             float gx, float gy, bool hiX)
{
    // ((g+1)*512 - 1) * 0.5 == g*256 + 255.5
    const float ix = fmaf(gx, 256.0f, 255.5f);
    const float iy = fmaf(gy, 256.0f, 255.5f);

    const float x0f = floorf(ix);
    const float y0f = floorf(iy);
    const float wx1 = ix - x0f, wx0 = 1.0f - wx1;
    const float wy1 = iy - y0f, wy0 = 1.0f - wy1;

    const int xi0 = (int)x0f;            // in [-1, 511]
    const int yi0 = (int)y0f;            // in [-1, 511]

    const unsigned bx = (unsigned)max(xi0, 0);
    const float wA = (xi0 >= 0) ? wx0 : wx1;                  // xi0==-1: base IS the x1 pixel
    const float wB = (xi0 >= 0 && xi0 < RES - 1) ? wx1 : 0.f;
    const float wlx = hiX ? wB : wA;

    const unsigned rA = (unsigned)max(yi0, 0);
    const float    vA = (yi0 >= 0) ? wy0 : 0.f;
    const unsigned rB = (unsigned)min(yi0 + 1, RES - 1);
    const float    vB = (yi0 + 1 <= RES - 1) ? wy1 : 0.f;

    // element offsets: (r*512 + bx)*32 = (r<<14) + (bx<<5)
    const unsigned bxs  = bx << 5;
    const uint4 rawA = __ldg(reinterpret_cast<const uint4*>(Tp + ((rA << 14) + bxs)));
    const uint4 rawB = __ldg(reinterpret_cast<const uint4*>(Tp + ((rB << 14) + bxs)));

    const __half2 va2 = __float2half2_rn(vA);
    const __half2 vb2 = __float2half2_rn(vB);
    const __half2* ha = reinterpret_cast<const __half2*>(&rawA);
    const __half2* hb = reinterpret_cast<const __half2*>(&rawB);

    #pragma unroll
    for (int i = 0; i < 4; ++i) {
        const __half2 t = __hfma2(hb[i], vb2, __hmul2(ha[i], va2));
        const float2 f  = __half22float2(t);
        acc[2 * i + 0] = fmaf(wlx, f.x, acc[2 * i + 0]);
        acc[2 * i + 1] = fmaf(wlx, f.y, acc[2 * i + 1]);
    }
}

__global__ __launch_bounds__(256, 6)
void sample_kernel(const float* __restrict__ x, float* __restrict__ out, int half)
{
    const int gid  = blockIdx.x * blockDim.x + threadIdx.x;
    const int grp  = gid >> 3;           // 8-lane group
    const int lane = gid & 7;
    if (grp >= half) return;

    const int  pt0 = grp;
    const int  pt1 = grp + half;
    const bool hiX = (lane >= 4);

    // coords (broadcast across the 8 lanes of each group)
    const float a0 = __ldg(x + (size_t)pt0 * 3 + 0);
    const float a1 = __ldg(x + (size_t)pt0 * 3 + 1);
    const float a2 = __ldg(x + (size_t)pt0 * 3 + 2);
    const float b0 = __ldg(x + (size_t)pt1 * 3 + 0);
    const float b1 = __ldg(x + (size_t)pt1 * 3 + 1);
    const float b2 = __ldg(x + (size_t)pt1 * 3 + 2);

    const float gxsA[3] = { a0, a0, a1 };
    const float gysA[3] = { a1, a2, a2 };
    const float gxsB[3] = { b0, b0, b1 };
    const float gysB[3] = { b1, b2, b2 };

    float acc0[8], acc1[8];
    #pragma unroll
    for (int i = 0; i < 8; ++i) { acc0[i] = 0.f; acc1[i] = 0.f; }

    const __half* Tl = g_Th + lane * 8;
    #pragma unroll
    for (int p = 0; p < 3; ++p) {
        const __half* Tp = Tl + ((unsigned)p << 23);   // p * 512*512*32
        plane_sample(acc0, Tp, gxsA[p], gysA[p], hiX);
        plane_sample(acc1, Tp, gxsB[p], gysB[p], hiX);
    }

    // Combine x0/x1 halves (lanes l and l^4 hold partials for channel group l&3)
    #pragma unroll
    for (int i = 0; i < 8; ++i) {
        acc0[i] += __shfl_xor_sync(0xffffffff, acc0[i], 4);
        acc1[i] += __shfl_xor_sync(0xffffffff, acc1[i], 4);
    }

    const int g = lane & 3;
    const int off = g * 8 + (hiX ? 4 : 0);
    float4 v0 = hiX ? make_float4(acc0[4], acc0[5], acc0[6], acc0[7])
                    : make_float4(acc0[0], acc0[1], acc0[2], acc0[3]);
    float4 v1 = hiX ? make_float4(acc1[4], acc1[5], acc1[6], acc1[7])
                    : make_float4(acc1[0], acc1[1], acc1[2], acc1[3]);
    __stwt(reinterpret_cast<float4*>(out + (size_t)pt0 * CFEAT + off), v0);
    __stwt(reinterpret_cast<float4*>(out + (size_t)pt1 * CFEAT + off), v1);
}

// ---------------------------------------------------------------------------
extern "C" void kernel_launch(void* const* d_in, const int* in_sizes, int n_in,
                              void* d_out, int out_size)
{
    const float* x_in  = (const float*)d_in[0];   // [N, 3]
    const float* c_mat = (const float*)d_in[1];   // [3, 32, 512, 512]
    float* out = (float*)d_out;                   // [N, 32]

    const int npts = in_sizes[0] / 3;
    const int half = npts / 2;

    dim3 tg(RES / 32, RES, 3);
    transpose_kernel<<<tg, 256>>>(c_mat);

    const int threads = 256;
    const long long total = (long long)half * 8;
    const int blocks = (int)((total + threads - 1) / threads);
    sample_kernel<<<blocks, threads>>>(x_in, out, half);
}

// round 17
// speedup vs baseline: 1.4581x; 1.0376x over previous
#include <cuda_runtime.h>
#include <cuda_fp16.h>
#include <cuda_bf16.h>
#include <cstdint>

// ---------------------------------------------------------------------------
// TriplaneEncoder: out[n][c] = sum_{p=0..2} bilinear(C_mat[p], coords_p(n))[c]
// Planes: p0:(x0,x1), p1:(x0,x2), p2:(x1,x2); gx = first (W axis), gy = second (H).
// align_corners=False, zero padding. RES=512, C=32, N=2097152.
//
// R16: R15 (8-lane 128B span gather, 2 pts/thread, fp16 y-blend) with
//      __launch_bounds__(256, 7): regs 40 -> <=36, occ 62.6% -> ~87% to close
//      the ~50us of unhidden gather latency the R15 profile shows.
// ---------------------------------------------------------------------------

#define RES   512
#define CFEAT 32

// 48 MB pixel-major fp16 table, +64 halves pad for the dead (weight-0) overread
// at bx=511 hiX span loads.
__device__ __half g_Th[3 * RES * RES * CFEAT + 64];

// ---------------------------------------------------------------------------
// Transpose+convert: src [p][c][y][x] f32 -> dst [p][y][x][c] f16.
// Block 256. grid = (16, 512, 3).
// ---------------------------------------------------------------------------
__global__ __launch_bounds__(256)
void transpose_kernel(const float* __restrict__ src)
{
    __shared__ float tile[32][33];   // [c][x], padded

    const int p  = blockIdx.z;
    const int y  = blockIdx.y;
    const int x0 = blockIdx.x * 32;
    const int t  = threadIdx.x;
    const int tx = t & 31;
    const int ty = t >> 5;

    const float* sp = src + ((size_t)p * CFEAT) * (RES * RES) + (size_t)y * RES + x0;
    #pragma unroll
    for (int c = ty; c < 32; c += 8) {
        tile[c][tx] = sp[(size_t)c * (RES * RES) + tx];
    }
    __syncthreads();

    const int xi  = t >> 3;              // 0..31 pixel within tile
    const int seg = t & 7;               // 0..7 channel quad

    struct __align__(8) H4 { __half2 a, b; };
    H4 packed;
    packed.a = __floats2half2_rn(tile[4 * seg + 0][xi], tile[4 * seg + 1][xi]);
    packed.b = __floats2half2_rn(tile[4 * seg + 2][xi], tile[4 * seg + 3][xi]);

    __half* dp = g_Th + (((size_t)p * RES + y) * RES + x0) * CFEAT;
    *reinterpret_cast<H4*>(dp + (size_t)xi * CFEAT + seg * 4) = packed;
}

// ---------------------------------------------------------------------------
// Sample kernel
// ---------------------------------------------------------------------------

// One plane for one point: two row-span loads, fp16 y-blend, fp32 x-weight FMA.
// Tp pre-offset by lane*8 halves.
__device__ __forceinline__ void plane_sample(float acc[8], const __half* __restrict__ Tp,
                                             float gx, float gy, bool hiX)
{
    // ((g+1)*512 - 1) * 0.5 == g*256 + 255.5
    const float ix = fmaf(gx, 256.0f, 255.5f);
    const float iy = fmaf(gy, 256.0f, 255.5f);

    const float x0f = floorf(ix);
    const float y0f = floorf(iy);
    const float wx1 = ix - x0f, wx0 = 1.0f - wx1;
    const float wy1 = iy - y0f, wy0 = 1.0f - wy1;

    const int xi0 = (int)x0f;            // in [-1, 511]
    const int yi0 = (int)y0f;            // in [-1, 511]

    const unsigned bx = (unsigned)max(xi0, 0);
    const float wA = (xi0 >= 0) ? wx0 : wx1;                  // xi0==-1: base IS the x1 pixel
    const float wB = (xi0 >= 0 && xi0 < RES - 1) ? wx1 : 0.f;
    const float wlx = hiX ? wB : wA;

    const unsigned rA = (unsigned)max(yi0, 0);
    const float    vA = (yi0 >= 0) ? wy0 : 0.f;
    const unsigned rB = (unsigned)min(yi0 + 1, RES - 1);
    const float    vB = (yi0 + 1 <= RES - 1) ? wy1 : 0.f;

    // element offsets: (r*512 + bx)*32 = (r<<14) + (bx<<5)
    const unsigned bxs  = bx << 5;
    const uint4 rawA = __ldg(reinterpret_cast<const uint4*>(Tp + ((rA << 14) + bxs)));
    const uint4 rawB = __ldg(reinterpret_cast<const uint4*>(Tp + ((rB << 14) + bxs)));

    const __half2 va2 = __float2half2_rn(vA);
    const __half2 vb2 = __float2half2_rn(vB);
    const __half2* ha = reinterpret_cast<const __half2*>(&rawA);
    const __half2* hb = reinterpret_cast<const __half2*>(&rawB);

    #pragma unroll
    for (int i = 0; i < 4; ++i) {
        const __half2 t = __hfma2(hb[i], vb2, __hmul2(ha[i], va2));
        const float2 f  = __half22float2(t);
        acc[2 * i + 0] = fmaf(wlx, f.x, acc[2 * i + 0]);
        acc[2 * i + 1] = fmaf(wlx, f.y, acc[2 * i + 1]);
    }
}

__global__ __launch_bounds__(256, 7)
void sample_kernel(const float* __restrict__ x, float* __restrict__ out, int half)
{
    const int gid  = blockIdx.x * blockDim.x + threadIdx.x;
    const int grp  = gid >> 3;           // 8-lane group
    const int lane = gid & 7;
    if (grp >= half) return;

    const int  pt0 = grp;
    const int  pt1 = grp + half;
    const bool hiX = (lane >= 4);

    // coords (broadcast across the 8 lanes of each group)
    const float a0 = __ldg(x + (size_t)pt0 * 3 + 0);
    const float a1 = __ldg(x + (size_t)pt0 * 3 + 1);
    const float a2 = __ldg(x + (size_t)pt0 * 3 + 2);
    const float b0 = __ldg(x + (size_t)pt1 * 3 + 0);
    const float b1 = __ldg(x + (size_t)pt1 * 3 + 1);
    const float b2 = __ldg(x + (size_t)pt1 * 3 + 2);

    const float gxsA[3] = { a0, a0, a1 };
    const float gysA[3] = { a1, a2, a2 };
    const float gxsB[3] = { b0, b0, b1 };
    const float gysB[3] = { b1, b2, b2 };

    float acc0[8], acc1[8];
    #pragma unroll
    for (int i = 0; i < 8; ++i) { acc0[i] = 0.f; acc1[i] = 0.f; }

    const __half* Tl = g_Th + lane * 8;
    #pragma unroll
    for (int p = 0; p < 3; ++p) {
        const __half* Tp = Tl + ((unsigned)p << 23);   // p * 512*512*32
        plane_sample(acc0, Tp, gxsA[p], gysA[p], hiX);
        plane_sample(acc1, Tp, gxsB[p], gysB[p], hiX);
    }

    // Combine x0/x1 halves (lanes l and l^4 hold partials for channel group l&3)
    #pragma unroll
    for (int i = 0; i < 8; ++i) {
        acc0[i] += __shfl_xor_sync(0xffffffff, acc0[i], 4);
        acc1[i] += __shfl_xor_sync(0xffffffff, acc1[i], 4);
    }

    const int g = lane & 3;
    const int off = g * 8 + (hiX ? 4 : 0);
    float4 v0 = hiX ? make_float4(acc0[4], acc0[5], acc0[6], acc0[7])
                    : make_float4(acc0[0], acc0[1], acc0[2], acc0[3]);
    float4 v1 = hiX ? make_float4(acc1[4], acc1[5], acc1[6], acc1[7])
                    : make_float4(acc1[0], acc1[1], acc1[2], acc1[3]);
    __stwt(reinterpret_cast<float4*>(out + (size_t)pt0 * CFEAT + off), v0);
    __stwt(reinterpret_cast<float4*>(out + (size_t)pt1 * CFEAT + off), v1);
}

// ---------------------------------------------------------------------------
extern "C" void kernel_launch(void* const* d_in, const int* in_sizes, int n_in,
                              void* d_out, int out_size)
{
    const float* x_in  = (const float*)d_in[0];   // [N, 3]
    const float* c_mat = (const float*)d_in[1];   // [3, 32, 512, 512]
    float* out = (float*)d_out;                   // [N, 32]

    const int npts = in_sizes[0] / 3;
    const int half = npts / 2;

    dim3 tg(RES / 32, RES, 3);
    transpose_kernel<<<tg, 256>>>(c_mat);

    const int threads = 256;
    const long long total = (long long)half * 8;
    const int blocks = (int)((total + threads - 1) / threads);
    sample_kernel<<<blocks, threads>>>(x_in, out, half);
}